// round 1
// baseline (speedup 1.0000x reference)
#include <cuda_runtime.h>

// Problem constants (fixed by the dataset)
#define B_ 8
#define T_ 2048
#define E_ 1024
#define C_ 128

// Scratch for projected Q, K, V  (8*2048*128 floats = 8 MB each)
__device__ float g_k[B_ * T_ * C_];
__device__ float g_q[B_ * T_ * C_];
__device__ float g_v[B_ * T_ * C_];

// ---------------------------------------------------------------------------
// Kernel 1: QKV projection.  Y[16384,128] = X[16384,1024] @ W[1024,128]
// grid = (256, 3): blockIdx.y selects which weight / destination.
// Block tile 64x128, BK=16, 256 threads, 4x8 register tile per thread.
// ---------------------------------------------------------------------------
__global__ __launch_bounds__(256) void qkv_kernel(
    const float* __restrict__ x,
    const float* __restrict__ Wk,
    const float* __restrict__ Wq,
    const float* __restrict__ Wv)
{
    const int w = blockIdx.y;
    const float* __restrict__ W = (w == 0) ? Wk : ((w == 1) ? Wq : Wv);
    float* dst = (w == 0) ? g_k : ((w == 1) ? g_q : g_v);

    __shared__ float Xs[64][16];
    __shared__ float Ws[16][132];   // padded to 132 floats per row

    const int tid = threadIdx.x;
    const int ty = tid >> 4;        // 0..15
    const int tx = tid & 15;        // 0..15
    const int m0 = blockIdx.x * 64;

    float acc[4][8];
#pragma unroll
    for (int i = 0; i < 4; i++)
#pragma unroll
        for (int j = 0; j < 8; j++) acc[i][j] = 0.f;

    const int xrow = tid >> 2;      // 0..63
    const int xc4  = tid & 3;       // which float4 of the 16-wide K slab

    for (int k0 = 0; k0 < E_; k0 += 16) {
        // load X tile 64x16 (one float4 per thread)
        float4 xv = *(const float4*)(x + (size_t)(m0 + xrow) * E_ + k0 + xc4 * 4);
        *(float4*)(&Xs[xrow][xc4 * 4]) = xv;
        // load W tile 16x128 (two float4 per thread)
#pragma unroll
        for (int e = 0; e < 2; e++) {
            int idx = tid + e * 256;          // float4 index, 32 per row
            int r = idx >> 5, c4 = idx & 31;
            float4 wv = *(const float4*)(W + (size_t)(k0 + r) * C_ + c4 * 4);
            *(float4*)(&Ws[r][c4 * 4]) = wv;
        }
        __syncthreads();

#pragma unroll
        for (int kk = 0; kk < 16; kk++) {
            float a[4];
#pragma unroll
            for (int i = 0; i < 4; i++) a[i] = Xs[ty * 4 + i][kk];
            float4 b0 = *(const float4*)(&Ws[kk][tx * 8]);
            float4 b1 = *(const float4*)(&Ws[kk][tx * 8 + 4]);
            float b[8] = {b0.x, b0.y, b0.z, b0.w, b1.x, b1.y, b1.z, b1.w};
#pragma unroll
            for (int i = 0; i < 4; i++)
#pragma unroll
                for (int j = 0; j < 8; j++)
                    acc[i][j] = fmaf(a[i], b[j], acc[i][j]);
        }
        __syncthreads();
    }

#pragma unroll
    for (int i = 0; i < 4; i++) {
        float4 o0 = make_float4(acc[i][0], acc[i][1], acc[i][2], acc[i][3]);
        float4 o1 = make_float4(acc[i][4], acc[i][5], acc[i][6], acc[i][7]);
        float* p = dst + (size_t)(m0 + ty * 4 + i) * C_ + tx * 8;
        *(float4*)(p)     = o0;
        *(float4*)(p + 4) = o1;
    }
}

// ---------------------------------------------------------------------------
// Kernel 2: causal flash attention.
// grid = 256 blocks: blockIdx.x = b*32 + qt  (64-query tile per block)
// 256 threads.  Per key tile (64 keys):
//   phase A: S = Q @ K^T  (64x64x128, 4x4 thread tile, Q/K transposed in smem)
//   softmax: online (rows owned by threads 0..63)
//   phase B: O += P @ V  (64x128x64, 4x8 thread tile)
// K and V share one smem buffer (sequenced by barriers) -> 2 CTAs/SM.
// ---------------------------------------------------------------------------
#define SM_QT   (128 * 65)          // Q transposed [128][65]
#define SM_KV   (64 * 132)          // K as [128][65] (8320) or V as [64][132] (8448)
#define SM_SS   (64 * 65)           // score/prob tile
#define ATTN_SMEM_FLOATS (SM_QT + SM_KV + SM_SS + 3 * 64)
#define ATTN_SMEM_BYTES  (ATTN_SMEM_FLOATS * 4)

__global__ __launch_bounds__(256) void attn_kernel(float* __restrict__ out)
{
    extern __shared__ float smp[];
    float* QT   = smp;                       // [128][65]
    float* KV   = smp + SM_QT;               // union: KT [128][65] / V [64][132]
    float* Ss   = KV + SM_KV;                // [64][65]
    float* mrow = Ss + SM_SS;                // [64]
    float* lrow = mrow + 64;                 // [64]
    float* srow = lrow + 64;                 // [64] rescale factors

    const int tid = threadIdx.x;
    const int ty = tid >> 4;                 // 0..15
    const int tx = tid & 15;                 // 0..15
    const int b  = blockIdx.x >> 5;
    const int qt = blockIdx.x & 31;

    // ---- load Q tile transposed into QT[d][r] ----
    const float4* qg = (const float4*)(g_q + (size_t)(b * T_ + qt * 64) * C_);
#pragma unroll
    for (int e = 0; e < 8; e++) {
        int idx = tid + e * 256;             // float4 index; 32 per row
        int r = idx >> 5, d4 = idx & 31;
        float4 v = qg[idx];
        QT[(d4 * 4 + 0) * 65 + r] = v.x;
        QT[(d4 * 4 + 1) * 65 + r] = v.y;
        QT[(d4 * 4 + 2) * 65 + r] = v.z;
        QT[(d4 * 4 + 3) * 65 + r] = v.w;
    }
    if (tid < 64) { mrow[tid] = -1e30f; lrow[tid] = 0.f; }

    float o[4][8];
#pragma unroll
    for (int i = 0; i < 4; i++)
#pragma unroll
        for (int j = 0; j < 8; j++) o[i][j] = 0.f;

    const float scale = 0.08838834764831845f;   // 1/sqrt(128)

    for (int kt = 0; kt <= qt; kt++) {
        __syncthreads();   // previous phase-B reads / QT load done

        // ---- load K tile transposed into KV as KT[d][r] ----
        const float4* kg = (const float4*)(g_k + (size_t)(b * T_ + kt * 64) * C_);
#pragma unroll
        for (int e = 0; e < 8; e++) {
            int idx = tid + e * 256;
            int r = idx >> 5, d4 = idx & 31;
            float4 v = kg[idx];
            KV[(d4 * 4 + 0) * 65 + r] = v.x;
            KV[(d4 * 4 + 1) * 65 + r] = v.y;
            KV[(d4 * 4 + 2) * 65 + r] = v.z;
            KV[(d4 * 4 + 3) * 65 + r] = v.w;
        }
        __syncthreads();

        // ---- phase A: S = Q @ K^T ----
        float s[4][4];
#pragma unroll
        for (int i = 0; i < 4; i++)
#pragma unroll
            for (int j = 0; j < 4; j++) s[i][j] = 0.f;

#pragma unroll 4
        for (int kk = 0; kk < 128; kk++) {
            float a[4], bb[4];
#pragma unroll
            for (int i = 0; i < 4; i++) a[i]  = QT[kk * 65 + ty * 4 + i];
#pragma unroll
            for (int j = 0; j < 4; j++) bb[j] = KV[kk * 65 + tx * 4 + j];
#pragma unroll
            for (int i = 0; i < 4; i++)
#pragma unroll
                for (int j = 0; j < 4; j++)
                    s[i][j] = fmaf(a[i], bb[j], s[i][j]);
        }

        const bool diag = (kt == qt);
#pragma unroll
        for (int i = 0; i < 4; i++)
#pragma unroll
            for (int j = 0; j < 4; j++) {
                float sv = s[i][j] * scale;
                if (diag && (tx * 4 + j) > (ty * 4 + i)) sv = -1e30f;
                Ss[(ty * 4 + i) * 65 + tx * 4 + j] = sv;
            }
        __syncthreads();   // S complete; phase-A reads of KV done

        // ---- load V tile into KV as V[r][d]  (overwrites KT) ----
        const float4* vg = (const float4*)(g_v + (size_t)(b * T_ + kt * 64) * C_);
#pragma unroll
        for (int e = 0; e < 8; e++) {
            int idx = tid + e * 256;
            int r = idx >> 5, d4 = idx & 31;
            *(float4*)(&KV[r * 132 + d4 * 4]) = vg[idx];
        }

        // ---- online softmax (one row per thread, threads 0..63) ----
        if (tid < 64) {
            const int r = tid;
            float rowmax = -1e30f;
#pragma unroll 8
            for (int c = 0; c < 64; c++)
                rowmax = fmaxf(rowmax, Ss[r * 65 + c]);
            float newm = fmaxf(mrow[r], rowmax);
            float fac  = __expf(mrow[r] - newm);
            float sum  = 0.f;
#pragma unroll 8
            for (int c = 0; c < 64; c++) {
                float p = __expf(Ss[r * 65 + c] - newm);
                Ss[r * 65 + c] = p;
                sum += p;
            }
            lrow[r] = lrow[r] * fac + sum;
            mrow[r] = newm;
            srow[r] = fac;
        }
        __syncthreads();   // probs + V + factors ready

        // ---- rescale accumulators ----
        float f[4];
#pragma unroll
        for (int i = 0; i < 4; i++) f[i] = srow[ty * 4 + i];
#pragma unroll
        for (int i = 0; i < 4; i++)
#pragma unroll
            for (int j = 0; j < 8; j++) o[i][j] *= f[i];

        // ---- phase B: O += P @ V ----
#pragma unroll 2
        for (int kk = 0; kk < 64; kk++) {
            float a[4];
#pragma unroll
            for (int i = 0; i < 4; i++) a[i] = Ss[(ty * 4 + i) * 65 + kk];
            float4 b0 = *(const float4*)(&KV[kk * 132 + tx * 8]);
            float4 b1 = *(const float4*)(&KV[kk * 132 + tx * 8 + 4]);
            float bb[8] = {b0.x, b0.y, b0.z, b0.w, b1.x, b1.y, b1.z, b1.w};
#pragma unroll
            for (int i = 0; i < 4; i++)
#pragma unroll
                for (int j = 0; j < 8; j++)
                    o[i][j] = fmaf(a[i], bb[j], o[i][j]);
        }
    }

    // ---- epilogue: normalize and store ----
#pragma unroll
    for (int i = 0; i < 4; i++) {
        float inv = 1.f / lrow[ty * 4 + i];
        float4 o0 = make_float4(o[i][0] * inv, o[i][1] * inv, o[i][2] * inv, o[i][3] * inv);
        float4 o1 = make_float4(o[i][4] * inv, o[i][5] * inv, o[i][6] * inv, o[i][7] * inv);
        float* p = out + (size_t)(b * T_ + qt * 64 + ty * 4 + i) * C_ + tx * 8;
        *(float4*)(p)     = o0;
        *(float4*)(p + 4) = o1;
    }
}

// ---------------------------------------------------------------------------
extern "C" void kernel_launch(void* const* d_in, const int* in_sizes, int n_in,
                              void* d_out, int out_size)
{
    const float* x  = (const float*)d_in[0];
    const float* Wk = (const float*)d_in[1];
    const float* Wq = (const float*)d_in[2];
    const float* Wv = (const float*)d_in[3];
    float* out = (float*)d_out;

    cudaFuncSetAttribute(attn_kernel,
                         cudaFuncAttributeMaxDynamicSharedMemorySize,
                         ATTN_SMEM_BYTES);

    dim3 qkv_grid((B_ * T_) / 64, 3);
    qkv_kernel<<<qkv_grid, 256>>>(x, Wk, Wq, Wv);

    attn_kernel<<<B_ * (T_ / 64), 256, ATTN_SMEM_BYTES>>>(out);
}

// round 2
// speedup vs baseline: 1.6958x; 1.6958x over previous
#include <cuda_runtime.h>
#include <cstdint>

#define B_ 8
#define T_ 2048
#define E_ 1024
#define C_ 128

// Scratch for projected Q, K, V (8 MB each)
__device__ float g_k[B_ * T_ * C_];
__device__ float g_q[B_ * T_ * C_];
__device__ float g_v[B_ * T_ * C_];

// ---------------------------------------------------------------------------
// tf32 helpers: split fp32 into hi+lo tf32 pair, 3-term mma for ~fp32 accuracy
// ---------------------------------------------------------------------------
__device__ __forceinline__ void f2tf(float x, uint32_t& h, uint32_t& l) {
    uint32_t hi; asm("cvt.rna.tf32.f32 %0, %1;" : "=r"(hi) : "f"(x));
    float r = x - __uint_as_float(hi);
    uint32_t lo; asm("cvt.rna.tf32.f32 %0, %1;" : "=r"(lo) : "f"(r));
    h = hi; l = lo;
}

__device__ __forceinline__ void mma8(float* c, const uint32_t* a, uint32_t b0, uint32_t b1) {
    asm volatile("mma.sync.aligned.m16n8k8.row.col.f32.tf32.tf32.f32 "
        "{%0,%1,%2,%3}, {%4,%5,%6,%7}, {%8,%9}, {%0,%1,%2,%3};"
        : "+f"(c[0]), "+f"(c[1]), "+f"(c[2]), "+f"(c[3])
        : "r"(a[0]), "r"(a[1]), "r"(a[2]), "r"(a[3]), "r"(b0), "r"(b1));
}

__device__ __forceinline__ void mma3(float* c, const uint32_t* ah, const uint32_t* al,
                                     uint32_t bh0, uint32_t bh1, uint32_t bl0, uint32_t bl1) {
    mma8(c, ah, bh0, bh1);
    mma8(c, al, bh0, bh1);
    mma8(c, ah, bl0, bl1);
}

// ---------------------------------------------------------------------------
// Kernel 1: QKV projection via split-tf32 mma.
// Y[16384,128] = X[16384,1024] @ W[1024,128].  grid=(128,3), 256 threads.
// Block tile 128x128, BK=16. 8 warps as 4(m) x 2(n): warp tile 32x64.
// ---------------------------------------------------------------------------
__global__ __launch_bounds__(256, 2) void qkv_mma(
    const float* __restrict__ x, const float* __restrict__ Wk,
    const float* __restrict__ Wq, const float* __restrict__ Wv)
{
    const int w = blockIdx.y;
    const float* __restrict__ W = (w == 0) ? Wk : ((w == 1) ? Wq : Wv);
    float* dst = (w == 0) ? g_k : ((w == 1) ? g_q : g_v);

    __shared__ float Xs[128][20];     // 128 rows x 16 cols, pad->20 (conflict-free A frags)
    __shared__ float Ws[16][132];     // 16 k x 128 n, pad->132 (2-way on B frags, ok)

    const int tid = threadIdx.x;
    const int wid = tid >> 5, lane = tid & 31, gid = lane >> 2, tig = lane & 3;
    const int wm = wid >> 1, wn = wid & 1;
    const int m0 = blockIdx.x * 128;

    float acc[2][8][4];
#pragma unroll
    for (int mt = 0; mt < 2; mt++)
#pragma unroll
        for (int nt = 0; nt < 8; nt++)
#pragma unroll
            for (int i = 0; i < 4; i++) acc[mt][nt][i] = 0.f;

    float4 px[2], pw[2];

    // load first tile
#pragma unroll
    for (int e = 0; e < 2; e++) {
        int idx = tid + e * 256;
        px[e] = *(const float4*)(x + (size_t)(m0 + (idx >> 2)) * E_ + (idx & 3) * 4);
        pw[e] = *(const float4*)(W + (size_t)(idx >> 5) * C_ + (idx & 31) * 4);
    }
#pragma unroll
    for (int e = 0; e < 2; e++) {
        int idx = tid + e * 256;
        *(float4*)(&Xs[idx >> 2][(idx & 3) * 4]) = px[e];
        *(float4*)(&Ws[idx >> 5][(idx & 31) * 4]) = pw[e];
    }
    __syncthreads();

    for (int it = 0; it < 64; it++) {
        const int knext = (it + 1) * 16;
        if (it < 63) {
#pragma unroll
            for (int e = 0; e < 2; e++) {
                int idx = tid + e * 256;
                px[e] = *(const float4*)(x + (size_t)(m0 + (idx >> 2)) * E_ + knext + (idx & 3) * 4);
                pw[e] = *(const float4*)(W + (size_t)(knext + (idx >> 5)) * C_ + (idx & 31) * 4);
            }
        }

#pragma unroll
        for (int ks = 0; ks < 2; ks++) {
            uint32_t ah[2][4], al[2][4];
#pragma unroll
            for (int mt = 0; mt < 2; mt++) {
                int r0 = wm * 32 + mt * 16 + gid;
                int c0 = ks * 8 + tig;
                f2tf(Xs[r0][c0],         ah[mt][0], al[mt][0]);
                f2tf(Xs[r0 + 8][c0],     ah[mt][1], al[mt][1]);
                f2tf(Xs[r0][c0 + 4],     ah[mt][2], al[mt][2]);
                f2tf(Xs[r0 + 8][c0 + 4], ah[mt][3], al[mt][3]);
            }
#pragma unroll
            for (int nt = 0; nt < 8; nt++) {
                int n = wn * 64 + nt * 8 + gid;
                uint32_t bh0, bl0, bh1, bl1;
                f2tf(Ws[ks * 8 + tig][n],     bh0, bl0);
                f2tf(Ws[ks * 8 + tig + 4][n], bh1, bl1);
#pragma unroll
                for (int mt = 0; mt < 2; mt++)
                    mma3(acc[mt][nt], ah[mt], al[mt], bh0, bh1, bl0, bl1);
            }
        }
        __syncthreads();

        if (it < 63) {
#pragma unroll
            for (int e = 0; e < 2; e++) {
                int idx = tid + e * 256;
                *(float4*)(&Xs[idx >> 2][(idx & 3) * 4]) = px[e];
                *(float4*)(&Ws[idx >> 5][(idx & 31) * 4]) = pw[e];
            }
            __syncthreads();
        }
    }

#pragma unroll
    for (int mt = 0; mt < 2; mt++) {
        int r0 = m0 + wm * 32 + mt * 16 + gid;
#pragma unroll
        for (int nt = 0; nt < 8; nt++) {
            int c = wn * 64 + nt * 8 + tig * 2;
            *(float2*)(dst + (size_t)r0 * C_ + c)       = make_float2(acc[mt][nt][0], acc[mt][nt][1]);
            *(float2*)(dst + (size_t)(r0 + 8) * C_ + c) = make_float2(acc[mt][nt][2], acc[mt][nt][3]);
        }
    }
}

// ---------------------------------------------------------------------------
// Kernel 2: causal flash attention via split-tf32 mma.
// grid = 256: blockIdx.x = b*32 + qt (64-query tiles), 256 threads, 8 warps.
// Phase A (QK^T): warps 4(m)x2(n), warp tile 16x32, k=128.
// Phase B (PV):   warps 4(m)x2(n), warp tile 16x64, k=64.
// K and V share one smem buffer (barrier-sequenced).
// ---------------------------------------------------------------------------
#define QSD 132
#define PSD 68
#define ATTN_SMEM_FLOATS (64 * QSD + 64 * QSD + 64 * PSD + 192)
#define ATTN_SMEM_BYTES  (ATTN_SMEM_FLOATS * 4)

__global__ __launch_bounds__(256, 2) void attn_mma(float* __restrict__ out)
{
    extern __shared__ float sm[];
    float* Qs   = sm;                    // [64][132] Q (queries x d)
    float* KVu  = sm + 64 * QSD;         // [64][132] K (keys x d) then V (keys x d)
    float* Ps   = KVu + 64 * QSD;        // [64][68]  scores / probs
    float* mrow = Ps + 64 * PSD;         // [64]
    float* lrow = mrow + 64;             // [64]
    float* srow = lrow + 64;             // [64]

    const int tid = threadIdx.x;
    const int wid = tid >> 5, lane = tid & 31, gid = lane >> 2, tig = lane & 3;
    const int wm = wid >> 1, wn = wid & 1;
    const int b = blockIdx.x >> 5, qt = blockIdx.x & 31;

    // load Q tile (straight copy, padded rows)
    const float4* qg = (const float4*)(g_q + (size_t)(b * T_ + qt * 64) * C_);
#pragma unroll
    for (int e = 0; e < 8; e++) {
        int idx = tid + e * 256;
        *(float4*)(&Qs[(idx >> 5) * QSD + (idx & 31) * 4]) = qg[idx];
    }
    if (tid < 64) { mrow[tid] = -1e30f; lrow[tid] = 0.f; }

    float o[8][4];
#pragma unroll
    for (int nt = 0; nt < 8; nt++)
#pragma unroll
        for (int i = 0; i < 4; i++) o[nt][i] = 0.f;

    const float scale = 0.08838834764831845f;   // 1/sqrt(128)

    for (int kt = 0; kt <= qt; kt++) {
        __syncthreads();   // KVu free (prev phase B done), Q visible on first iter

        // load K tile
        const float4* kg = (const float4*)(g_k + (size_t)(b * T_ + kt * 64) * C_);
#pragma unroll
        for (int e = 0; e < 8; e++) {
            int idx = tid + e * 256;
            *(float4*)(&KVu[(idx >> 5) * QSD + (idx & 31) * 4]) = kg[idx];
        }
        __syncthreads();

        // ---- phase A: S = Q @ K^T via split-tf32 ----
        float s[4][4];
#pragma unroll
        for (int nt = 0; nt < 4; nt++)
#pragma unroll
            for (int i = 0; i < 4; i++) s[nt][i] = 0.f;

        const int r0 = wm * 16 + gid;
#pragma unroll 4
        for (int ks = 0; ks < 16; ks++) {
            uint32_t ah[4], al[4];
            int c0 = ks * 8 + tig;
            f2tf(Qs[r0 * QSD + c0],           ah[0], al[0]);
            f2tf(Qs[(r0 + 8) * QSD + c0],     ah[1], al[1]);
            f2tf(Qs[r0 * QSD + c0 + 4],       ah[2], al[2]);
            f2tf(Qs[(r0 + 8) * QSD + c0 + 4], ah[3], al[3]);
#pragma unroll
            for (int nt = 0; nt < 4; nt++) {
                int n = wn * 32 + nt * 8 + gid;
                uint32_t bh0, bl0, bh1, bl1;
                f2tf(KVu[n * QSD + c0],     bh0, bl0);
                f2tf(KVu[n * QSD + c0 + 4], bh1, bl1);
                mma3(s[nt], ah, al, bh0, bh1, bl0, bl1);
            }
        }

        // scale + causal mask + store S -> Ps
        const bool diag = (kt == qt);
#pragma unroll
        for (int nt = 0; nt < 4; nt++) {
            int kb = wn * 32 + nt * 8 + tig * 2;
            float v0 = s[nt][0] * scale, v1 = s[nt][1] * scale;
            float v2 = s[nt][2] * scale, v3 = s[nt][3] * scale;
            if (diag) {
                if (kb     > r0)     v0 = -1e30f;
                if (kb + 1 > r0)     v1 = -1e30f;
                if (kb     > r0 + 8) v2 = -1e30f;
                if (kb + 1 > r0 + 8) v3 = -1e30f;
            }
            Ps[r0 * PSD + kb]           = v0;
            Ps[r0 * PSD + kb + 1]       = v1;
            Ps[(r0 + 8) * PSD + kb]     = v2;
            Ps[(r0 + 8) * PSD + kb + 1] = v3;
        }
        __syncthreads();   // all K reads done, Ps complete

        // load V tile into KVu (overwrites K)
        const float4* vg = (const float4*)(g_v + (size_t)(b * T_ + kt * 64) * C_);
#pragma unroll
        for (int e = 0; e < 8; e++) {
            int idx = tid + e * 256;
            *(float4*)(&KVu[(idx >> 5) * QSD + (idx & 31) * 4]) = vg[idx];
        }

        // ---- online softmax: 4 threads per row ----
        {
            int r = tid >> 2, seg = tid & 3;
            float* pr = Ps + r * PSD + seg * 16;
            float4 p0 = *(float4*)(pr), p1 = *(float4*)(pr + 4);
            float4 p2 = *(float4*)(pr + 8), p3 = *(float4*)(pr + 12);
            float mx = fmaxf(fmaxf(fmaxf(p0.x, p0.y), fmaxf(p0.z, p0.w)),
                     fmaxf(fmaxf(fmaxf(p1.x, p1.y), fmaxf(p1.z, p1.w)),
                     fmaxf(fmaxf(fmaxf(p2.x, p2.y), fmaxf(p2.z, p2.w)),
                           fmaxf(fmaxf(p3.x, p3.y), fmaxf(p3.z, p3.w)))));
            mx = fmaxf(mx, __shfl_xor_sync(0xffffffffu, mx, 1));
            mx = fmaxf(mx, __shfl_xor_sync(0xffffffffu, mx, 2));
            float mold = mrow[r];
            float newm = fmaxf(mold, mx);
            float fac  = __expf(mold - newm);
            float sum;
            p0.x = __expf(p0.x - newm); p0.y = __expf(p0.y - newm);
            p0.z = __expf(p0.z - newm); p0.w = __expf(p0.w - newm);
            p1.x = __expf(p1.x - newm); p1.y = __expf(p1.y - newm);
            p1.z = __expf(p1.z - newm); p1.w = __expf(p1.w - newm);
            p2.x = __expf(p2.x - newm); p2.y = __expf(p2.y - newm);
            p2.z = __expf(p2.z - newm); p2.w = __expf(p2.w - newm);
            p3.x = __expf(p3.x - newm); p3.y = __expf(p3.y - newm);
            p3.z = __expf(p3.z - newm); p3.w = __expf(p3.w - newm);
            sum = (p0.x + p0.y + p0.z + p0.w) + (p1.x + p1.y + p1.z + p1.w)
                + (p2.x + p2.y + p2.z + p2.w) + (p3.x + p3.y + p3.z + p3.w);
            *(float4*)(pr)      = p0;
            *(float4*)(pr + 4)  = p1;
            *(float4*)(pr + 8)  = p2;
            *(float4*)(pr + 12) = p3;
            sum += __shfl_xor_sync(0xffffffffu, sum, 1);
            sum += __shfl_xor_sync(0xffffffffu, sum, 2);
            if (seg == 0) {
                lrow[r] = lrow[r] * fac + sum;
                mrow[r] = newm;
                srow[r] = fac;
            }
        }
        __syncthreads();   // V visible, probs + stats ready

        // rescale accumulators
        {
            float f0 = srow[r0], f1 = srow[r0 + 8];
#pragma unroll
            for (int nt = 0; nt < 8; nt++) {
                o[nt][0] *= f0; o[nt][1] *= f0;
                o[nt][2] *= f1; o[nt][3] *= f1;
            }
        }

        // ---- phase B: O += P @ V via split-tf32 ----
#pragma unroll 2
        for (int ks = 0; ks < 8; ks++) {
            uint32_t ah[4], al[4];
            int c0 = ks * 8 + tig;
            f2tf(Ps[r0 * PSD + c0],           ah[0], al[0]);
            f2tf(Ps[(r0 + 8) * PSD + c0],     ah[1], al[1]);
            f2tf(Ps[r0 * PSD + c0 + 4],       ah[2], al[2]);
            f2tf(Ps[(r0 + 8) * PSD + c0 + 4], ah[3], al[3]);
#pragma unroll
            for (int nt = 0; nt < 8; nt++) {
                int n = wn * 64 + nt * 8 + gid;
                uint32_t bh0, bl0, bh1, bl1;
                f2tf(KVu[(ks * 8 + tig) * QSD + n],     bh0, bl0);
                f2tf(KVu[(ks * 8 + tig + 4) * QSD + n], bh1, bl1);
                mma3(o[nt], ah, al, bh0, bh1, bl0, bl1);
            }
        }
    }

    // epilogue: normalize and store
    {
        int r0 = wm * 16 + gid;
        float inv0 = 1.f / lrow[r0], inv1 = 1.f / lrow[r0 + 8];
        size_t base = (size_t)(b * T_ + qt * 64);
#pragma unroll
        for (int nt = 0; nt < 8; nt++) {
            int c = wn * 64 + nt * 8 + tig * 2;
            *(float2*)(out + (base + r0) * C_ + c)     = make_float2(o[nt][0] * inv0, o[nt][1] * inv0);
            *(float2*)(out + (base + r0 + 8) * C_ + c) = make_float2(o[nt][2] * inv1, o[nt][3] * inv1);
        }
    }
}

// ---------------------------------------------------------------------------
extern "C" void kernel_launch(void* const* d_in, const int* in_sizes, int n_in,
                              void* d_out, int out_size)
{
    const float* x  = (const float*)d_in[0];
    const float* Wk = (const float*)d_in[1];
    const float* Wq = (const float*)d_in[2];
    const float* Wv = (const float*)d_in[3];
    float* out = (float*)d_out;

    cudaFuncSetAttribute(attn_mma,
                         cudaFuncAttributeMaxDynamicSharedMemorySize,
                         ATTN_SMEM_BYTES);

    dim3 qkv_grid(128, 3);
    qkv_mma<<<qkv_grid, 256>>>(x, Wk, Wq, Wv);

    attn_mma<<<B_ * (T_ / 64), 256, ATTN_SMEM_BYTES>>>(out);
}

// round 3
// speedup vs baseline: 2.0459x; 1.2065x over previous
#include <cuda_runtime.h>
#include <cstdint>

#define B_ 8
#define T_ 2048
#define E_ 1024
#define C_ 128

// Scratch for projected Q, K, V (8 MB each)
__device__ float g_k[B_ * T_ * C_];
__device__ float g_q[B_ * T_ * C_];
__device__ float g_v[B_ * T_ * C_];

// ---------------------------------------------------------------------------
// tf32 helpers
// ---------------------------------------------------------------------------
__device__ __forceinline__ void f2tf(float x, uint32_t& h, uint32_t& l) {
    uint32_t hi; asm("cvt.rna.tf32.f32 %0, %1;" : "=r"(hi) : "f"(x));
    float r = x - __uint_as_float(hi);
    uint32_t lo; asm("cvt.rna.tf32.f32 %0, %1;" : "=r"(lo) : "f"(r));
    h = hi; l = lo;
}

__device__ __forceinline__ float2 splitf(float x) {
    uint32_t h, l; f2tf(x, h, l);
    return make_float2(__uint_as_float(h), __uint_as_float(l));
}

__device__ __forceinline__ void mma8(float* c, const uint32_t* a, uint32_t b0, uint32_t b1) {
    asm volatile("mma.sync.aligned.m16n8k8.row.col.f32.tf32.tf32.f32 "
        "{%0,%1,%2,%3}, {%4,%5,%6,%7}, {%8,%9}, {%0,%1,%2,%3};"
        : "+f"(c[0]), "+f"(c[1]), "+f"(c[2]), "+f"(c[3])
        : "r"(a[0]), "r"(a[1]), "r"(a[2]), "r"(a[3]), "r"(b0), "r"(b1));
}

// 3-term split mma: hi*hi + lo*hi + hi*lo
__device__ __forceinline__ void mma3(float* c, const uint32_t* ah, const uint32_t* al,
                                     uint32_t bh0, uint32_t bh1, uint32_t bl0, uint32_t bl1) {
    mma8(c, ah, bh0, bh1);
    mma8(c, al, bh0, bh1);
    mma8(c, ah, bl0, bl1);
}

#define U_(f) __float_as_uint(f)

// ---------------------------------------------------------------------------
// Kernel 1: QKV projection, pre-split smem.
// Y[16384,128] = X[16384,1024] @ W[1024,128].  grid=(128,3), 256 threads.
// Block tile 128x128, BK=16. 8 warps 4(m)x2(n), warp tile 32x64.
// Xs2: float2[128][20]  (stride 20 f2: 20 % 16 == 4 -> conflict-free LDS.64)
// Ws2: float2[16][132]  (132 % 16 == 4)
// ---------------------------------------------------------------------------
__global__ __launch_bounds__(256, 2) void qkv_mma(
    const float* __restrict__ x, const float* __restrict__ Wk,
    const float* __restrict__ Wq, const float* __restrict__ Wv)
{
    const int w = blockIdx.y;
    const float* __restrict__ W = (w == 0) ? Wk : ((w == 1) ? Wq : Wv);
    float* dst = (w == 0) ? g_k : ((w == 1) ? g_q : g_v);

    __shared__ float2 Xs2[128 * 20];
    __shared__ float2 Ws2[16 * 132];

    const int tid = threadIdx.x;
    const int wid = tid >> 5, lane = tid & 31, gid = lane >> 2, tig = lane & 3;
    const int wm = wid >> 1, wn = wid & 1;
    const int m0 = blockIdx.x * 128;

    float acc[2][8][4];
#pragma unroll
    for (int mt = 0; mt < 2; mt++)
#pragma unroll
        for (int nt = 0; nt < 8; nt++)
#pragma unroll
            for (int i = 0; i < 4; i++) acc[mt][nt][i] = 0.f;

    float4 px[2], pw[2];

#pragma unroll
    for (int e = 0; e < 2; e++) {
        int idx = tid + e * 256;
        px[e] = *(const float4*)(x + (size_t)(m0 + (idx >> 2)) * E_ + (idx & 3) * 4);
        pw[e] = *(const float4*)(W + (size_t)(idx >> 5) * C_ + (idx & 31) * 4);
    }
#pragma unroll
    for (int e = 0; e < 2; e++) {
        int idx = tid + e * 256;
        float2* xd = &Xs2[(idx >> 2) * 20 + (idx & 3) * 4];
        xd[0] = splitf(px[e].x); xd[1] = splitf(px[e].y);
        xd[2] = splitf(px[e].z); xd[3] = splitf(px[e].w);
        float2* wd = &Ws2[(idx >> 5) * 132 + (idx & 31) * 4];
        wd[0] = splitf(pw[e].x); wd[1] = splitf(pw[e].y);
        wd[2] = splitf(pw[e].z); wd[3] = splitf(pw[e].w);
    }
    __syncthreads();

    for (int it = 0; it < 64; it++) {
        const int knext = (it + 1) * 16;
        if (it < 63) {
#pragma unroll
            for (int e = 0; e < 2; e++) {
                int idx = tid + e * 256;
                px[e] = *(const float4*)(x + (size_t)(m0 + (idx >> 2)) * E_ + knext + (idx & 3) * 4);
                pw[e] = *(const float4*)(W + (size_t)(knext + (idx >> 5)) * C_ + (idx & 31) * 4);
            }
        }

#pragma unroll
        for (int ks = 0; ks < 2; ks++) {
            const int c0 = ks * 8 + tig;
            uint32_t ah[2][4], al[2][4];
#pragma unroll
            for (int mt = 0; mt < 2; mt++) {
                int r0 = wm * 32 + mt * 16 + gid;
                float2 a0 = Xs2[r0 * 20 + c0];
                float2 a1 = Xs2[(r0 + 8) * 20 + c0];
                float2 a2 = Xs2[r0 * 20 + c0 + 4];
                float2 a3 = Xs2[(r0 + 8) * 20 + c0 + 4];
                ah[mt][0] = U_(a0.x); al[mt][0] = U_(a0.y);
                ah[mt][1] = U_(a1.x); al[mt][1] = U_(a1.y);
                ah[mt][2] = U_(a2.x); al[mt][2] = U_(a2.y);
                ah[mt][3] = U_(a3.x); al[mt][3] = U_(a3.y);
            }
#pragma unroll
            for (int nt = 0; nt < 8; nt++) {
                int n = wn * 64 + nt * 8 + gid;
                float2 b0 = Ws2[(ks * 8 + tig) * 132 + n];
                float2 b1 = Ws2[(ks * 8 + tig + 4) * 132 + n];
#pragma unroll
                for (int mt = 0; mt < 2; mt++)
                    mma3(acc[mt][nt], ah[mt], al[mt], U_(b0.x), U_(b1.x), U_(b0.y), U_(b1.y));
            }
        }
        __syncthreads();

        if (it < 63) {
#pragma unroll
            for (int e = 0; e < 2; e++) {
                int idx = tid + e * 256;
                float2* xd = &Xs2[(idx >> 2) * 20 + (idx & 3) * 4];
                xd[0] = splitf(px[e].x); xd[1] = splitf(px[e].y);
                xd[2] = splitf(px[e].z); xd[3] = splitf(px[e].w);
                float2* wd = &Ws2[(idx >> 5) * 132 + (idx & 31) * 4];
                wd[0] = splitf(pw[e].x); wd[1] = splitf(pw[e].y);
                wd[2] = splitf(pw[e].z); wd[3] = splitf(pw[e].w);
            }
            __syncthreads();
        }
    }

#pragma unroll
    for (int mt = 0; mt < 2; mt++) {
        int r0 = m0 + wm * 32 + mt * 16 + gid;
#pragma unroll
        for (int nt = 0; nt < 8; nt++) {
            int c = wn * 64 + nt * 8 + tig * 2;
            *(float2*)(dst + (size_t)r0 * C_ + c)       = make_float2(acc[mt][nt][0], acc[mt][nt][1]);
            *(float2*)(dst + (size_t)(r0 + 8) * C_ + c) = make_float2(acc[mt][nt][2], acc[mt][nt][3]);
        }
    }
}

// ---------------------------------------------------------------------------
// Kernel 2: causal flash attention, pre-split smem, 1 CTA/SM.
// Qs2/KV2: float2[64][132]  (132 % 16 == 4 -> conflict-free 64-bit LDS)
// Ps: fp32 [64][68].  LPT launch order: qt descending.
// ---------------------------------------------------------------------------
#define QS2D 132
#define PSD 68
#define ATTN_SMEM_BYTES (2 * (64 * QS2D * 8) + 64 * PSD * 4 + 192 * 4)

__global__ __launch_bounds__(256, 1) void attn_mma(float* __restrict__ out)
{
    extern __shared__ float sm[];
    float2* Qs2  = (float2*)sm;                        // [64][132] hi/lo
    float2* KV2  = Qs2 + 64 * QS2D;                    // [64][132] K then V
    float*  Ps   = (float*)(KV2 + 64 * QS2D);          // [64][68]
    float*  mrow = Ps + 64 * PSD;
    float*  lrow = mrow + 64;
    float*  srow = lrow + 64;

    const int tid = threadIdx.x;
    const int wid = tid >> 5, lane = tid & 31, gid = lane >> 2, tig = lane & 3;
    const int wm = wid >> 1, wn = wid & 1;
    // LPT: heaviest (largest qt) CTAs first
    const int qt = 31 - (blockIdx.x >> 3);
    const int b  = blockIdx.x & 7;

    // load + split Q tile
    const float4* qg = (const float4*)(g_q + (size_t)(b * T_ + qt * 64) * C_);
#pragma unroll
    for (int e = 0; e < 8; e++) {
        int idx = tid + e * 256;
        float4 v = qg[idx];
        float2* d = &Qs2[(idx >> 5) * QS2D + (idx & 31) * 4];
        d[0] = splitf(v.x); d[1] = splitf(v.y); d[2] = splitf(v.z); d[3] = splitf(v.w);
    }
    if (tid < 64) { mrow[tid] = -1e30f; lrow[tid] = 0.f; }

    float o[8][4];
#pragma unroll
    for (int nt = 0; nt < 8; nt++)
#pragma unroll
        for (int i = 0; i < 4; i++) o[nt][i] = 0.f;

    const float scale = 0.08838834764831845f;   // 1/sqrt(128)
    const int r0 = wm * 16 + gid;

    for (int kt = 0; kt <= qt; kt++) {
        __syncthreads();   // KV2 free (prev phase B done); Qs2 visible on iter 0

        // load + split K tile
        const float4* kg = (const float4*)(g_k + (size_t)(b * T_ + kt * 64) * C_);
#pragma unroll
        for (int e = 0; e < 8; e++) {
            int idx = tid + e * 256;
            float4 v = kg[idx];
            float2* d = &KV2[(idx >> 5) * QS2D + (idx & 31) * 4];
            d[0] = splitf(v.x); d[1] = splitf(v.y); d[2] = splitf(v.z); d[3] = splitf(v.w);
        }
        __syncthreads();

        // ---- phase A: S = Q @ K^T ----
        float s[4][4];
#pragma unroll
        for (int nt = 0; nt < 4; nt++)
#pragma unroll
            for (int i = 0; i < 4; i++) s[nt][i] = 0.f;

#pragma unroll 4
        for (int ks = 0; ks < 16; ks++) {
            const int c0 = ks * 8 + tig;
            uint32_t ah[4], al[4];
            float2 a0 = Qs2[r0 * QS2D + c0];
            float2 a1 = Qs2[(r0 + 8) * QS2D + c0];
            float2 a2 = Qs2[r0 * QS2D + c0 + 4];
            float2 a3 = Qs2[(r0 + 8) * QS2D + c0 + 4];
            ah[0] = U_(a0.x); al[0] = U_(a0.y);
            ah[1] = U_(a1.x); al[1] = U_(a1.y);
            ah[2] = U_(a2.x); al[2] = U_(a2.y);
            ah[3] = U_(a3.x); al[3] = U_(a3.y);
#pragma unroll
            for (int nt = 0; nt < 4; nt++) {
                int n = wn * 32 + nt * 8 + gid;
                float2 b0 = KV2[n * QS2D + c0];
                float2 b1 = KV2[n * QS2D + c0 + 4];
                mma3(s[nt], ah, al, U_(b0.x), U_(b1.x), U_(b0.y), U_(b1.y));
            }
        }

        // scale + causal mask + store S -> Ps
        const bool diag = (kt == qt);
#pragma unroll
        for (int nt = 0; nt < 4; nt++) {
            int kb = wn * 32 + nt * 8 + tig * 2;
            float v0 = s[nt][0] * scale, v1 = s[nt][1] * scale;
            float v2 = s[nt][2] * scale, v3 = s[nt][3] * scale;
            if (diag) {
                if (kb     > r0)     v0 = -1e30f;
                if (kb + 1 > r0)     v1 = -1e30f;
                if (kb     > r0 + 8) v2 = -1e30f;
                if (kb + 1 > r0 + 8) v3 = -1e30f;
            }
            Ps[r0 * PSD + kb]           = v0;
            Ps[r0 * PSD + kb + 1]       = v1;
            Ps[(r0 + 8) * PSD + kb]     = v2;
            Ps[(r0 + 8) * PSD + kb + 1] = v3;
        }
        __syncthreads();   // Ps complete; K reads done

        // load + split V tile (overwrites K)
        const float4* vg = (const float4*)(g_v + (size_t)(b * T_ + kt * 64) * C_);
#pragma unroll
        for (int e = 0; e < 8; e++) {
            int idx = tid + e * 256;
            float4 v = vg[idx];
            float2* d = &KV2[(idx >> 5) * QS2D + (idx & 31) * 4];
            d[0] = splitf(v.x); d[1] = splitf(v.y); d[2] = splitf(v.z); d[3] = splitf(v.w);
        }

        // ---- online softmax: 4 threads per row ----
        {
            int r = tid >> 2, seg = tid & 3;
            float* pr = Ps + r * PSD + seg * 16;
            float4 p0 = *(float4*)(pr), p1 = *(float4*)(pr + 4);
            float4 p2 = *(float4*)(pr + 8), p3 = *(float4*)(pr + 12);
            float mx = fmaxf(fmaxf(fmaxf(p0.x, p0.y), fmaxf(p0.z, p0.w)),
                     fmaxf(fmaxf(fmaxf(p1.x, p1.y), fmaxf(p1.z, p1.w)),
                     fmaxf(fmaxf(fmaxf(p2.x, p2.y), fmaxf(p2.z, p2.w)),
                           fmaxf(fmaxf(p3.x, p3.y), fmaxf(p3.z, p3.w)))));
            mx = fmaxf(mx, __shfl_xor_sync(0xffffffffu, mx, 1));
            mx = fmaxf(mx, __shfl_xor_sync(0xffffffffu, mx, 2));
            float mold = mrow[r];
            float newm = fmaxf(mold, mx);
            float fac  = __expf(mold - newm);
            p0.x = __expf(p0.x - newm); p0.y = __expf(p0.y - newm);
            p0.z = __expf(p0.z - newm); p0.w = __expf(p0.w - newm);
            p1.x = __expf(p1.x - newm); p1.y = __expf(p1.y - newm);
            p1.z = __expf(p1.z - newm); p1.w = __expf(p1.w - newm);
            p2.x = __expf(p2.x - newm); p2.y = __expf(p2.y - newm);
            p2.z = __expf(p2.z - newm); p2.w = __expf(p2.w - newm);
            p3.x = __expf(p3.x - newm); p3.y = __expf(p3.y - newm);
            p3.z = __expf(p3.z - newm); p3.w = __expf(p3.w - newm);
            float sum = (p0.x + p0.y + p0.z + p0.w) + (p1.x + p1.y + p1.z + p1.w)
                      + (p2.x + p2.y + p2.z + p2.w) + (p3.x + p3.y + p3.z + p3.w);
            *(float4*)(pr)      = p0;
            *(float4*)(pr + 4)  = p1;
            *(float4*)(pr + 8)  = p2;
            *(float4*)(pr + 12) = p3;
            sum += __shfl_xor_sync(0xffffffffu, sum, 1);
            sum += __shfl_xor_sync(0xffffffffu, sum, 2);
            if (seg == 0) {
                lrow[r] = lrow[r] * fac + sum;
                mrow[r] = newm;
                srow[r] = fac;
            }
        }
        __syncthreads();   // V split visible, probs + stats ready

        // rescale accumulators
        {
            float f0 = srow[r0], f1 = srow[r0 + 8];
#pragma unroll
            for (int nt = 0; nt < 8; nt++) {
                o[nt][0] *= f0; o[nt][1] *= f0;
                o[nt][2] *= f1; o[nt][3] *= f1;
            }
        }

        // ---- phase B: O += P @ V ----
#pragma unroll 2
        for (int ks = 0; ks < 8; ks++) {
            const int c0 = ks * 8 + tig;
            uint32_t ah[4], al[4];
            f2tf(Ps[r0 * PSD + c0],           ah[0], al[0]);
            f2tf(Ps[(r0 + 8) * PSD + c0],     ah[1], al[1]);
            f2tf(Ps[r0 * PSD + c0 + 4],       ah[2], al[2]);
            f2tf(Ps[(r0 + 8) * PSD + c0 + 4], ah[3], al[3]);
#pragma unroll
            for (int nt = 0; nt < 8; nt++) {
                int n = wn * 64 + nt * 8 + gid;
                float2 b0 = KV2[(ks * 8 + tig) * QS2D + n];
                float2 b1 = KV2[(ks * 8 + tig + 4) * QS2D + n];
                mma3(o[nt], ah, al, U_(b0.x), U_(b1.x), U_(b0.y), U_(b1.y));
            }
        }
    }

    // epilogue
    {
        float inv0 = 1.f / lrow[r0], inv1 = 1.f / lrow[r0 + 8];
        size_t base = (size_t)(b * T_ + qt * 64);
#pragma unroll
        for (int nt = 0; nt < 8; nt++) {
            int c = wn * 64 + nt * 8 + tig * 2;
            *(float2*)(out + (base + r0) * C_ + c)     = make_float2(o[nt][0] * inv0, o[nt][1] * inv0);
            *(float2*)(out + (base + r0 + 8) * C_ + c) = make_float2(o[nt][2] * inv1, o[nt][3] * inv1);
        }
    }
}

// ---------------------------------------------------------------------------
extern "C" void kernel_launch(void* const* d_in, const int* in_sizes, int n_in,
                              void* d_out, int out_size)
{
    const float* x  = (const float*)d_in[0];
    const float* Wk = (const float*)d_in[1];
    const float* Wq = (const float*)d_in[2];
    const float* Wv = (const float*)d_in[3];
    float* out = (float*)d_out;

    cudaFuncSetAttribute(attn_mma,
                         cudaFuncAttributeMaxDynamicSharedMemorySize,
                         ATTN_SMEM_BYTES);

    dim3 qkv_grid(128, 3);
    qkv_mma<<<qkv_grid, 256>>>(x, Wk, Wq, Wv);

    attn_mma<<<B_ * (T_ / 64), 256, ATTN_SMEM_BYTES>>>(out);
}

// round 6
// speedup vs baseline: 3.3672x; 1.6459x over previous
#include <cuda_runtime.h>
#include <cstdint>

#define B_ 8
#define T_ 2048
#define E_ 1024
#define C_ 128

// Scratch for projected Q, K, V (8 MB each)
__device__ float g_k[B_ * T_ * C_];
__device__ float g_q[B_ * T_ * C_];
__device__ float g_v[B_ * T_ * C_];

// ---------------------------------------------------------------------------
// tf32 helpers
// ---------------------------------------------------------------------------
__device__ __forceinline__ float tfr(float x) {
    uint32_t h; asm("cvt.rna.tf32.f32 %0, %1;" : "=r"(h) : "f"(x));
    return __uint_as_float(h);
}
__device__ __forceinline__ float4 tfr4(float4 v) {
    return make_float4(tfr(v.x), tfr(v.y), tfr(v.z), tfr(v.w));
}
__device__ __forceinline__ void mma8(float* c, const uint32_t* a, uint32_t b0, uint32_t b1) {
    asm volatile("mma.sync.aligned.m16n8k8.row.col.f32.tf32.tf32.f32 "
        "{%0,%1,%2,%3}, {%4,%5,%6,%7}, {%8,%9}, {%0,%1,%2,%3};"
        : "+f"(c[0]), "+f"(c[1]), "+f"(c[2]), "+f"(c[3])
        : "r"(a[0]), "r"(a[1]), "r"(a[2]), "r"(a[3]), "r"(b0), "r"(b1));
}
#define U_(f) __float_as_uint(f)

// ---------------------------------------------------------------------------
// Kernel 1: QKV projection, plain tf32 mma.sync.
// Y[16384,128] = X[16384,1024] @ W[1024,128].  grid=(128,3), 256 threads.
// Block tile 128x128, BK=32. 8 warps 4(m)x2(n), warp tile 32x64.
// Xs: [128][36] (stride 36 -> conflict-free A frags), Ws: [32][132].
// Operands stored tf32-rounded; inner loop = pure LDS + HMMA.
// ---------------------------------------------------------------------------
__global__ __launch_bounds__(256, 2) void qkv_mma(
    const float* __restrict__ x, const float* __restrict__ Wk,
    const float* __restrict__ Wq, const float* __restrict__ Wv)
{
    const int w = blockIdx.y;
    const float* __restrict__ W = (w == 0) ? Wk : ((w == 1) ? Wq : Wv);
    float* dst = (w == 0) ? g_k : ((w == 1) ? g_q : g_v);

    __shared__ float Xs[128 * 36];
    __shared__ float Ws[32 * 132];

    const int tid = threadIdx.x;
    const int wid = tid >> 5, lane = tid & 31, gid = lane >> 2, tig = lane & 3;
    const int wm = wid >> 1, wn = wid & 1;
    const int m0 = blockIdx.x * 128;

    float acc[2][8][4];
#pragma unroll
    for (int mt = 0; mt < 2; mt++)
#pragma unroll
        for (int nt = 0; nt < 8; nt++)
#pragma unroll
            for (int i = 0; i < 4; i++) acc[mt][nt][i] = 0.f;

    float4 px[4], pw[4];

    // ---- load tile 0 ----
#pragma unroll
    for (int e = 0; e < 4; e++) {
        int idx = tid + e * 256;
        // A: 128 rows x 32 cols = 1024 float4: row = idx>>3, c4 = idx&7
        px[e] = *(const float4*)(x + (size_t)(m0 + (idx >> 3)) * E_ + (idx & 7) * 4);
        // B: 32 rows x 128 cols = 1024 float4: row = idx>>5, c4 = idx&31
        pw[e] = *(const float4*)(W + (size_t)(idx >> 5) * C_ + (idx & 31) * 4);
    }
#pragma unroll
    for (int e = 0; e < 4; e++) {
        int idx = tid + e * 256;
        *(float4*)(&Xs[(idx >> 3) * 36 + (idx & 7) * 4])   = tfr4(px[e]);
        *(float4*)(&Ws[(idx >> 5) * 132 + (idx & 31) * 4]) = tfr4(pw[e]);
    }
    __syncthreads();

    for (int it = 0; it < 32; it++) {
        if (it < 31) {
            const int k0 = (it + 1) * 32;
#pragma unroll
            for (int e = 0; e < 4; e++) {
                int idx = tid + e * 256;
                px[e] = *(const float4*)(x + (size_t)(m0 + (idx >> 3)) * E_ + k0 + (idx & 7) * 4);
                pw[e] = *(const float4*)(W + (size_t)(k0 + (idx >> 5)) * C_ + (idx & 31) * 4);
            }
        }

#pragma unroll
        for (int ks = 0; ks < 4; ks++) {
            const int c0 = ks * 8 + tig;
            uint32_t a[2][4];
#pragma unroll
            for (int mt = 0; mt < 2; mt++) {
                int r0 = wm * 32 + mt * 16 + gid;
                a[mt][0] = U_(Xs[r0 * 36 + c0]);
                a[mt][1] = U_(Xs[(r0 + 8) * 36 + c0]);
                a[mt][2] = U_(Xs[r0 * 36 + c0 + 4]);
                a[mt][3] = U_(Xs[(r0 + 8) * 36 + c0 + 4]);
            }
#pragma unroll
            for (int nt = 0; nt < 8; nt++) {
                int n = wn * 64 + nt * 8 + gid;
                uint32_t b0 = U_(Ws[(ks * 8 + tig) * 132 + n]);
                uint32_t b1 = U_(Ws[(ks * 8 + tig + 4) * 132 + n]);
#pragma unroll
                for (int mt = 0; mt < 2; mt++)
                    mma8(acc[mt][nt], a[mt], b0, b1);
            }
        }
        __syncthreads();

        if (it < 31) {
#pragma unroll
            for (int e = 0; e < 4; e++) {
                int idx = tid + e * 256;
                *(float4*)(&Xs[(idx >> 3) * 36 + (idx & 7) * 4])   = tfr4(px[e]);
                *(float4*)(&Ws[(idx >> 5) * 132 + (idx & 31) * 4]) = tfr4(pw[e]);
            }
            __syncthreads();
        }
    }

#pragma unroll
    for (int mt = 0; mt < 2; mt++) {
        int r0 = m0 + wm * 32 + mt * 16 + gid;
#pragma unroll
        for (int nt = 0; nt < 8; nt++) {
            int c = wn * 64 + nt * 8 + tig * 2;
            *(float2*)(dst + (size_t)r0 * C_ + c)       = make_float2(acc[mt][nt][0], acc[mt][nt][1]);
            *(float2*)(dst + (size_t)(r0 + 8) * C_ + c) = make_float2(acc[mt][nt][2], acc[mt][nt][3]);
        }
    }
}

// ---------------------------------------------------------------------------
// Kernel 2: causal flash attention, plain tf32 mma.sync, 2 CTA/SM.
// Qs/KV: [64][132] tf32-rounded floats.  Ps: fp32 [64][68].
// bid mapping: co-resident pair (bid, bid+148) has qt sum == 31 (balanced SMs).
// ---------------------------------------------------------------------------
#define QSD 132
#define PSD 68
#define ATTN_SMEM_BYTES ((64 * QSD + 64 * QSD + 64 * PSD + 192) * 4)

__global__ __launch_bounds__(256, 2) void attn_mma(float* __restrict__ out)
{
    extern __shared__ float sm[];
    float* Qs   = sm;                    // [64][132]
    float* KV   = sm + 64 * QSD;         // [64][132] K then V
    float* Ps   = KV + 64 * QSD;         // [64][68]
    float* mrow = Ps + 64 * PSD;
    float* lrow = mrow + 64;
    float* srow = lrow + 64;

    const int tid = threadIdx.x;
    const int wid = tid >> 5, lane = tid & 31, gid = lane >> 2, tig = lane & 3;
    const int wm = wid >> 1, wn = wid & 1;

    // balanced mapping: bids b and b+148 co-located by classic-launch LUT;
    // their qt's sum to 31 -> equal per-SM work.
    const int bb = blockIdx.x;
    int b, qt;
    if (bb < 128) { b = bb >> 5;              qt = 31 - (bb & 31); }
    else          { b = 4 + ((bb - 128) >> 5); qt = ((bb & 31) + 12) & 31; }

    // ---- load Q tile (tf32-rounded) ----
    const float4* qg = (const float4*)(g_q + (size_t)(b * T_ + qt * 64) * C_);
#pragma unroll
    for (int e = 0; e < 8; e++) {
        int idx = tid + e * 256;
        *(float4*)(&Qs[(idx >> 5) * QSD + (idx & 31) * 4]) = tfr4(qg[idx]);
    }
    if (tid < 64) { mrow[tid] = -1e30f; lrow[tid] = 0.f; }

    float o[8][4];
#pragma unroll
    for (int nt = 0; nt < 8; nt++)
#pragma unroll
        for (int i = 0; i < 4; i++) o[nt][i] = 0.f;

    const float scale = 0.08838834764831845f;   // 1/sqrt(128)
    const int r0 = wm * 16 + gid;

    for (int kt = 0; kt <= qt; kt++) {
        __syncthreads();   // KV free (prev phase B done); Qs visible on iter 0

        // ---- load K tile ----
        const float4* kg = (const float4*)(g_k + (size_t)(b * T_ + kt * 64) * C_);
#pragma unroll
        for (int e = 0; e < 8; e++) {
            int idx = tid + e * 256;
            *(float4*)(&KV[(idx >> 5) * QSD + (idx & 31) * 4]) = tfr4(kg[idx]);
        }
        __syncthreads();

        // ---- phase A: S = Q @ K^T ----
        float s[4][4];
#pragma unroll
        for (int nt = 0; nt < 4; nt++)
#pragma unroll
            for (int i = 0; i < 4; i++) s[nt][i] = 0.f;

#pragma unroll 4
        for (int ks = 0; ks < 16; ks++) {
            const int c0 = ks * 8 + tig;
            uint32_t a[4];
            a[0] = U_(Qs[r0 * QSD + c0]);
            a[1] = U_(Qs[(r0 + 8) * QSD + c0]);
            a[2] = U_(Qs[r0 * QSD + c0 + 4]);
            a[3] = U_(Qs[(r0 + 8) * QSD + c0 + 4]);
#pragma unroll
            for (int nt = 0; nt < 4; nt++) {
                int n = wn * 32 + nt * 8 + gid;
                uint32_t b0 = U_(KV[n * QSD + c0]);
                uint32_t b1 = U_(KV[n * QSD + c0 + 4]);
                mma8(s[nt], a, b0, b1);
            }
        }

        // scale + causal mask + store S -> Ps
        const bool diag = (kt == qt);
#pragma unroll
        for (int nt = 0; nt < 4; nt++) {
            int kb = wn * 32 + nt * 8 + tig * 2;
            float v0 = s[nt][0] * scale, v1 = s[nt][1] * scale;
            float v2 = s[nt][2] * scale, v3 = s[nt][3] * scale;
            if (diag) {
                if (kb     > r0)     v0 = -1e30f;
                if (kb + 1 > r0)     v1 = -1e30f;
                if (kb     > r0 + 8) v2 = -1e30f;
                if (kb + 1 > r0 + 8) v3 = -1e30f;
            }
            Ps[r0 * PSD + kb]           = v0;
            Ps[r0 * PSD + kb + 1]       = v1;
            Ps[(r0 + 8) * PSD + kb]     = v2;
            Ps[(r0 + 8) * PSD + kb + 1] = v3;
        }
        __syncthreads();   // Ps complete; K reads done

        // ---- load V tile (overwrites K) ----
        const float4* vg = (const float4*)(g_v + (size_t)(b * T_ + kt * 64) * C_);
#pragma unroll
        for (int e = 0; e < 8; e++) {
            int idx = tid + e * 256;
            *(float4*)(&KV[(idx >> 5) * QSD + (idx & 31) * 4]) = tfr4(vg[idx]);
        }

        // ---- online softmax: 4 threads per row ----
        {
            int r = tid >> 2, seg = tid & 3;
            float* pr = Ps + r * PSD + seg * 16;
            float4 p0 = *(float4*)(pr), p1 = *(float4*)(pr + 4);
            float4 p2 = *(float4*)(pr + 8), p3 = *(float4*)(pr + 12);
            float mx = fmaxf(fmaxf(fmaxf(p0.x, p0.y), fmaxf(p0.z, p0.w)),
                     fmaxf(fmaxf(fmaxf(p1.x, p1.y), fmaxf(p1.z, p1.w)),
                     fmaxf(fmaxf(fmaxf(p2.x, p2.y), fmaxf(p2.z, p2.w)),
                           fmaxf(fmaxf(p3.x, p3.y), fmaxf(p3.z, p3.w)))));
            mx = fmaxf(mx, __shfl_xor_sync(0xffffffffu, mx, 1));
            mx = fmaxf(mx, __shfl_xor_sync(0xffffffffu, mx, 2));
            float mold = mrow[r];
            float newm = fmaxf(mold, mx);
            float fac  = __expf(mold - newm);
            p0.x = __expf(p0.x - newm); p0.y = __expf(p0.y - newm);
            p0.z = __expf(p0.z - newm); p0.w = __expf(p0.w - newm);
            p1.x = __expf(p1.x - newm); p1.y = __expf(p1.y - newm);
            p1.z = __expf(p1.z - newm); p1.w = __expf(p1.w - newm);
            p2.x = __expf(p2.x - newm); p2.y = __expf(p2.y - newm);
            p2.z = __expf(p2.z - newm); p2.w = __expf(p2.w - newm);
            p3.x = __expf(p3.x - newm); p3.y = __expf(p3.y - newm);
            p3.z = __expf(p3.z - newm); p3.w = __expf(p3.w - newm);
            float sum = (p0.x + p0.y + p0.z + p0.w) + (p1.x + p1.y + p1.z + p1.w)
                      + (p2.x + p2.y + p2.z + p2.w) + (p3.x + p3.y + p3.z + p3.w);
            *(float4*)(pr)      = p0;
            *(float4*)(pr + 4)  = p1;
            *(float4*)(pr + 8)  = p2;
            *(float4*)(pr + 12) = p3;
            sum += __shfl_xor_sync(0xffffffffu, sum, 1);
            sum += __shfl_xor_sync(0xffffffffu, sum, 2);
            if (seg == 0) {
                lrow[r] = lrow[r] * fac + sum;
                mrow[r] = newm;
                srow[r] = fac;
            }
        }
        __syncthreads();   // V visible, probs + stats ready

        // rescale accumulators
        {
            float f0 = srow[r0], f1 = srow[r0 + 8];
#pragma unroll
            for (int nt = 0; nt < 8; nt++) {
                o[nt][0] *= f0; o[nt][1] *= f0;
                o[nt][2] *= f1; o[nt][3] *= f1;
            }
        }

        // ---- phase B: O += P @ V ----
#pragma unroll 2
        for (int ks = 0; ks < 8; ks++) {
            const int c0 = ks * 8 + tig;
            uint32_t a[4];
            a[0] = U_(tfr(Ps[r0 * PSD + c0]));
            a[1] = U_(tfr(Ps[(r0 + 8) * PSD + c0]));
            a[2] = U_(tfr(Ps[r0 * PSD + c0 + 4]));
            a[3] = U_(tfr(Ps[(r0 + 8) * PSD + c0 + 4]));
#pragma unroll
            for (int nt = 0; nt < 8; nt++) {
                int n = wn * 64 + nt * 8 + gid;
                uint32_t b0 = U_(KV[(ks * 8 + tig) * QSD + n]);
                uint32_t b1 = U_(KV[(ks * 8 + tig + 4) * QSD + n]);
                mma8(o[nt], a, b0, b1);
            }
        }
    }

    // ---- epilogue: normalize and store ----
    {
        float inv0 = 1.f / lrow[r0], inv1 = 1.f / lrow[r0 + 8];
        size_t base = (size_t)(b * T_ + qt * 64);
#pragma unroll
        for (int nt = 0; nt < 8; nt++) {
            int c = wn * 64 + nt * 8 + tig * 2;
            *(float2*)(out + (base + r0) * C_ + c)     = make_float2(o[nt][0] * inv0, o[nt][1] * inv0);
            *(float2*)(out + (base + r0 + 8) * C_ + c) = make_float2(o[nt][2] * inv1, o[nt][3] * inv1);
        }
    }
}

// ---------------------------------------------------------------------------
extern "C" void kernel_launch(void* const* d_in, const int* in_sizes, int n_in,
                              void* d_out, int out_size)
{
    const float* x  = (const float*)d_in[0];
    const float* Wk = (const float*)d_in[1];
    const float* Wq = (const float*)d_in[2];
    const float* Wv = (const float*)d_in[3];
    float* out = (float*)d_out;

    cudaFuncSetAttribute(attn_mma,
                         cudaFuncAttributeMaxDynamicSharedMemorySize,
                         ATTN_SMEM_BYTES);

    dim3 qkv_grid(128, 3);
    qkv_mma<<<qkv_grid, 256>>>(x, Wk, Wq, Wv);

    attn_mma<<<B_ * (T_ / 64), 256, ATTN_SMEM_BYTES>>>(out);
}

// round 7
// speedup vs baseline: 3.3823x; 1.0045x over previous
#include <cuda_runtime.h>
#include <cstdint>

#define B_ 8
#define T_ 2048
#define E_ 1024
#define C_ 128

// Scratch for projected Q, K, V (8 MB each)
__device__ float g_k[B_ * T_ * C_];
__device__ float g_q[B_ * T_ * C_];
__device__ float g_v[B_ * T_ * C_];

// ---------------------------------------------------------------------------
// tf32 helpers
// ---------------------------------------------------------------------------
__device__ __forceinline__ float tfr(float x) {
    uint32_t h; asm("cvt.rna.tf32.f32 %0, %1;" : "=r"(h) : "f"(x));
    return __uint_as_float(h);
}
__device__ __forceinline__ float4 tfr4(float4 v) {
    return make_float4(tfr(v.x), tfr(v.y), tfr(v.z), tfr(v.w));
}
__device__ __forceinline__ void mma8(float* c, const uint32_t* a, uint32_t b0, uint32_t b1) {
    asm volatile("mma.sync.aligned.m16n8k8.row.col.f32.tf32.tf32.f32 "
        "{%0,%1,%2,%3}, {%4,%5,%6,%7}, {%8,%9}, {%0,%1,%2,%3};"
        : "+f"(c[0]), "+f"(c[1]), "+f"(c[2]), "+f"(c[3])
        : "r"(a[0]), "r"(a[1]), "r"(a[2]), "r"(a[3]), "r"(b0), "r"(b1));
}
#define U_(f) __float_as_uint(f)

// ---------------------------------------------------------------------------
// Kernel 1: QKV projection, plain tf32 mma.sync (unchanged from R6).
// ---------------------------------------------------------------------------
__global__ __launch_bounds__(256, 2) void qkv_mma(
    const float* __restrict__ x, const float* __restrict__ Wk,
    const float* __restrict__ Wq, const float* __restrict__ Wv)
{
    const int w = blockIdx.y;
    const float* __restrict__ W = (w == 0) ? Wk : ((w == 1) ? Wq : Wv);
    float* dst = (w == 0) ? g_k : ((w == 1) ? g_q : g_v);

    __shared__ float Xs[128 * 36];
    __shared__ float Ws[32 * 132];

    const int tid = threadIdx.x;
    const int wid = tid >> 5, lane = tid & 31, gid = lane >> 2, tig = lane & 3;
    const int wm = wid >> 1, wn = wid & 1;
    const int m0 = blockIdx.x * 128;

    float acc[2][8][4];
#pragma unroll
    for (int mt = 0; mt < 2; mt++)
#pragma unroll
        for (int nt = 0; nt < 8; nt++)
#pragma unroll
            for (int i = 0; i < 4; i++) acc[mt][nt][i] = 0.f;

    float4 px[4], pw[4];

#pragma unroll
    for (int e = 0; e < 4; e++) {
        int idx = tid + e * 256;
        px[e] = *(const float4*)(x + (size_t)(m0 + (idx >> 3)) * E_ + (idx & 7) * 4);
        pw[e] = *(const float4*)(W + (size_t)(idx >> 5) * C_ + (idx & 31) * 4);
    }
#pragma unroll
    for (int e = 0; e < 4; e++) {
        int idx = tid + e * 256;
        *(float4*)(&Xs[(idx >> 3) * 36 + (idx & 7) * 4])   = tfr4(px[e]);
        *(float4*)(&Ws[(idx >> 5) * 132 + (idx & 31) * 4]) = tfr4(pw[e]);
    }
    __syncthreads();

    for (int it = 0; it < 32; it++) {
        if (it < 31) {
            const int k0 = (it + 1) * 32;
#pragma unroll
            for (int e = 0; e < 4; e++) {
                int idx = tid + e * 256;
                px[e] = *(const float4*)(x + (size_t)(m0 + (idx >> 3)) * E_ + k0 + (idx & 7) * 4);
                pw[e] = *(const float4*)(W + (size_t)(k0 + (idx >> 5)) * C_ + (idx & 31) * 4);
            }
        }

#pragma unroll
        for (int ks = 0; ks < 4; ks++) {
            const int c0 = ks * 8 + tig;
            uint32_t a[2][4];
#pragma unroll
            for (int mt = 0; mt < 2; mt++) {
                int r0 = wm * 32 + mt * 16 + gid;
                a[mt][0] = U_(Xs[r0 * 36 + c0]);
                a[mt][1] = U_(Xs[(r0 + 8) * 36 + c0]);
                a[mt][2] = U_(Xs[r0 * 36 + c0 + 4]);
                a[mt][3] = U_(Xs[(r0 + 8) * 36 + c0 + 4]);
            }
#pragma unroll
            for (int nt = 0; nt < 8; nt++) {
                int n = wn * 64 + nt * 8 + gid;
                uint32_t b0 = U_(Ws[(ks * 8 + tig) * 132 + n]);
                uint32_t b1 = U_(Ws[(ks * 8 + tig + 4) * 132 + n]);
#pragma unroll
                for (int mt = 0; mt < 2; mt++)
                    mma8(acc[mt][nt], a[mt], b0, b1);
            }
        }
        __syncthreads();

        if (it < 31) {
#pragma unroll
            for (int e = 0; e < 4; e++) {
                int idx = tid + e * 256;
                *(float4*)(&Xs[(idx >> 3) * 36 + (idx & 7) * 4])   = tfr4(px[e]);
                *(float4*)(&Ws[(idx >> 5) * 132 + (idx & 31) * 4]) = tfr4(pw[e]);
            }
            __syncthreads();
        }
    }

#pragma unroll
    for (int mt = 0; mt < 2; mt++) {
        int r0 = m0 + wm * 32 + mt * 16 + gid;
#pragma unroll
        for (int nt = 0; nt < 8; nt++) {
            int c = wn * 64 + nt * 8 + tig * 2;
            *(float2*)(dst + (size_t)r0 * C_ + c)       = make_float2(acc[mt][nt][0], acc[mt][nt][1]);
            *(float2*)(dst + (size_t)(r0 + 8) * C_ + c) = make_float2(acc[mt][nt][2], acc[mt][nt][3]);
        }
    }
}

// ---------------------------------------------------------------------------
// Kernel 2: causal flash attention, tf32 mma.sync, 2 CTA/SM,
// register-prefetched K/V (LDG latency off the critical path).
// Per tile: V LDG issued at phase-A start; K[kt+1] LDG issued after V STS.
// ---------------------------------------------------------------------------
#define QSD 132
#define PSD 68
#define ATTN_SMEM_BYTES ((64 * QSD + 64 * QSD + 64 * PSD + 192) * 4)

__global__ __launch_bounds__(256, 2) void attn_mma(float* __restrict__ out)
{
    extern __shared__ float sm[];
    float* Qs   = sm;                    // [64][132]
    float* KV   = sm + 64 * QSD;         // [64][132] K then V (union)
    float* Ps   = KV + 64 * QSD;         // [64][68]
    float* mrow = Ps + 64 * PSD;
    float* lrow = mrow + 64;
    float* srow = lrow + 64;

    const int tid = threadIdx.x;
    const int wid = tid >> 5, lane = tid & 31, gid = lane >> 2, tig = lane & 3;
    const int wm = wid >> 1, wn = wid & 1;

    // balanced mapping: co-resident pair (bid, bid+148) has qt sum == 31
    const int bb = blockIdx.x;
    int b, qt;
    if (bb < 128) { b = bb >> 5;               qt = 31 - (bb & 31); }
    else          { b = 4 + ((bb - 128) >> 5); qt = ((bb & 31) + 12) & 31; }

    const int ldr = tid >> 5;            // load row group: idx>>5
    const int ldc = (tid & 31) * 4;      // load col

    // ---- prologue: load Q tile + prefetch K[0] ----
    const float4* qg = (const float4*)(g_q + (size_t)(b * T_ + qt * 64) * C_);
    float4 kreg[8];
    {
        const float4* kg = (const float4*)(g_k + (size_t)(b * T_) * C_);
#pragma unroll
        for (int e = 0; e < 8; e++) kreg[e] = kg[tid + e * 256];
    }
#pragma unroll
    for (int e = 0; e < 8; e++) {
        int idx = tid + e * 256;
        *(float4*)(&Qs[(idx >> 5) * QSD + (idx & 31) * 4]) = tfr4(qg[idx]);
    }
    if (tid < 64) { mrow[tid] = -1e30f; lrow[tid] = 0.f; }
    __syncthreads();
    // STS K[0]
#pragma unroll
    for (int e = 0; e < 8; e++) {
        int idx = tid + e * 256;
        *(float4*)(&KV[(idx >> 5) * QSD + (idx & 31) * 4]) = tfr4(kreg[e]);
    }
    __syncthreads();   // K visible

    float o[8][4];
#pragma unroll
    for (int nt = 0; nt < 8; nt++)
#pragma unroll
        for (int i = 0; i < 4; i++) o[nt][i] = 0.f;

    const float scale = 0.08838834764831845f;   // 1/sqrt(128)
    const int r0 = wm * 16 + gid;

    for (int kt = 0; kt <= qt; kt++) {
        // ---- issue V[kt] LDG (consumed after sync c) ----
        float4 vreg[8];
        {
            const float4* vg = (const float4*)(g_v + (size_t)(b * T_ + kt * 64) * C_);
#pragma unroll
            for (int e = 0; e < 8; e++) vreg[e] = vg[tid + e * 256];
        }

        // ---- phase A: S = Q @ K^T ----
        float s[4][4];
#pragma unroll
        for (int nt = 0; nt < 4; nt++)
#pragma unroll
            for (int i = 0; i < 4; i++) s[nt][i] = 0.f;

#pragma unroll 4
        for (int ks = 0; ks < 16; ks++) {
            const int c0 = ks * 8 + tig;
            uint32_t a[4];
            a[0] = U_(Qs[r0 * QSD + c0]);
            a[1] = U_(Qs[(r0 + 8) * QSD + c0]);
            a[2] = U_(Qs[r0 * QSD + c0 + 4]);
            a[3] = U_(Qs[(r0 + 8) * QSD + c0 + 4]);
#pragma unroll
            for (int nt = 0; nt < 4; nt++) {
                int n = wn * 32 + nt * 8 + gid;
                uint32_t b0 = U_(KV[n * QSD + c0]);
                uint32_t b1 = U_(KV[n * QSD + c0 + 4]);
                mma8(s[nt], a, b0, b1);
            }
        }

        // scale + causal mask + store S -> Ps
        const bool diag = (kt == qt);
#pragma unroll
        for (int nt = 0; nt < 4; nt++) {
            int kb = wn * 32 + nt * 8 + tig * 2;
            float v0 = s[nt][0] * scale, v1 = s[nt][1] * scale;
            float v2 = s[nt][2] * scale, v3 = s[nt][3] * scale;
            if (diag) {
                if (kb     > r0)     v0 = -1e30f;
                if (kb + 1 > r0)     v1 = -1e30f;
                if (kb     > r0 + 8) v2 = -1e30f;
                if (kb + 1 > r0 + 8) v3 = -1e30f;
            }
            Ps[r0 * PSD + kb]           = v0;
            Ps[r0 * PSD + kb + 1]       = v1;
            Ps[(r0 + 8) * PSD + kb]     = v2;
            Ps[(r0 + 8) * PSD + kb + 1] = v3;
        }
        __syncthreads();   // (c) Ps complete; K reads done

        // ---- STS V (overwrites K in union) ----
#pragma unroll
        for (int e = 0; e < 8; e++) {
            int idx = tid + e * 256;
            *(float4*)(&KV[(idx >> 5) * QSD + (idx & 31) * 4]) = tfr4(vreg[e]);
        }

        // ---- issue K[kt+1] LDG (consumed after phase B) ----
        if (kt < qt) {
            const float4* kg = (const float4*)(g_k + (size_t)(b * T_ + (kt + 1) * 64) * C_);
#pragma unroll
            for (int e = 0; e < 8; e++) kreg[e] = kg[tid + e * 256];
        }

        // ---- online softmax: 4 threads per row ----
        {
            int r = tid >> 2, seg = tid & 3;
            float* pr = Ps + r * PSD + seg * 16;
            float4 p0 = *(float4*)(pr), p1 = *(float4*)(pr + 4);
            float4 p2 = *(float4*)(pr + 8), p3 = *(float4*)(pr + 12);
            float mx = fmaxf(fmaxf(fmaxf(p0.x, p0.y), fmaxf(p0.z, p0.w)),
                     fmaxf(fmaxf(fmaxf(p1.x, p1.y), fmaxf(p1.z, p1.w)),
                     fmaxf(fmaxf(fmaxf(p2.x, p2.y), fmaxf(p2.z, p2.w)),
                           fmaxf(fmaxf(p3.x, p3.y), fmaxf(p3.z, p3.w)))));
            mx = fmaxf(mx, __shfl_xor_sync(0xffffffffu, mx, 1));
            mx = fmaxf(mx, __shfl_xor_sync(0xffffffffu, mx, 2));
            float mold = mrow[r];
            float newm = fmaxf(mold, mx);
            float fac  = __expf(mold - newm);
            p0.x = __expf(p0.x - newm); p0.y = __expf(p0.y - newm);
            p0.z = __expf(p0.z - newm); p0.w = __expf(p0.w - newm);
            p1.x = __expf(p1.x - newm); p1.y = __expf(p1.y - newm);
            p1.z = __expf(p1.z - newm); p1.w = __expf(p1.w - newm);
            p2.x = __expf(p2.x - newm); p2.y = __expf(p2.y - newm);
            p2.z = __expf(p2.z - newm); p2.w = __expf(p2.w - newm);
            p3.x = __expf(p3.x - newm); p3.y = __expf(p3.y - newm);
            p3.z = __expf(p3.z - newm); p3.w = __expf(p3.w - newm);
            float sum = (p0.x + p0.y + p0.z + p0.w) + (p1.x + p1.y + p1.z + p1.w)
                      + (p2.x + p2.y + p2.z + p2.w) + (p3.x + p3.y + p3.z + p3.w);
            *(float4*)(pr)      = p0;
            *(float4*)(pr + 4)  = p1;
            *(float4*)(pr + 8)  = p2;
            *(float4*)(pr + 12) = p3;
            sum += __shfl_xor_sync(0xffffffffu, sum, 1);
            sum += __shfl_xor_sync(0xffffffffu, sum, 2);
            if (seg == 0) {
                lrow[r] = lrow[r] * fac + sum;
                mrow[r] = newm;
                srow[r] = fac;
            }
        }
        __syncthreads();   // (d) V visible, probs + stats ready

        // ---- rescale accumulators ----
        {
            float f0 = srow[r0], f1 = srow[r0 + 8];
#pragma unroll
            for (int nt = 0; nt < 8; nt++) {
                o[nt][0] *= f0; o[nt][1] *= f0;
                o[nt][2] *= f1; o[nt][3] *= f1;
            }
        }

        // ---- phase B: O += P @ V ----
#pragma unroll 2
        for (int ks = 0; ks < 8; ks++) {
            const int c0 = ks * 8 + tig;
            uint32_t a[4];
            a[0] = U_(tfr(Ps[r0 * PSD + c0]));
            a[1] = U_(tfr(Ps[(r0 + 8) * PSD + c0]));
            a[2] = U_(tfr(Ps[r0 * PSD + c0 + 4]));
            a[3] = U_(tfr(Ps[(r0 + 8) * PSD + c0 + 4]));
#pragma unroll
            for (int nt = 0; nt < 8; nt++) {
                int n = wn * 64 + nt * 8 + gid;
                uint32_t b0 = U_(KV[(ks * 8 + tig) * QSD + n]);
                uint32_t b1 = U_(KV[(ks * 8 + tig + 4) * QSD + n]);
                mma8(o[nt], a, b0, b1);
            }
        }
        __syncthreads();   // (a) phase B done; KV free

        // ---- STS K[kt+1] ----
        if (kt < qt) {
#pragma unroll
            for (int e = 0; e < 8; e++) {
                int idx = tid + e * 256;
                *(float4*)(&KV[(idx >> 5) * QSD + (idx & 31) * 4]) = tfr4(kreg[e]);
            }
        }
        __syncthreads();   // (b) K visible
    }

    // ---- epilogue: normalize and store ----
    {
        float inv0 = 1.f / lrow[r0], inv1 = 1.f / lrow[r0 + 8];
        size_t base = (size_t)(b * T_ + qt * 64);
#pragma unroll
        for (int nt = 0; nt < 8; nt++) {
            int c = wn * 64 + nt * 8 + tig * 2;
            *(float2*)(out + (base + r0) * C_ + c)     = make_float2(o[nt][0] * inv0, o[nt][1] * inv0);
            *(float2*)(out + (base + r0 + 8) * C_ + c) = make_float2(o[nt][2] * inv1, o[nt][3] * inv1);
        }
    }
}

// ---------------------------------------------------------------------------
extern "C" void kernel_launch(void* const* d_in, const int* in_sizes, int n_in,
                              void* d_out, int out_size)
{
    const float* x  = (const float*)d_in[0];
    const float* Wk = (const float*)d_in[1];
    const float* Wq = (const float*)d_in[2];
    const float* Wv = (const float*)d_in[3];
    float* out = (float*)d_out;

    cudaFuncSetAttribute(attn_mma,
                         cudaFuncAttributeMaxDynamicSharedMemorySize,
                         ATTN_SMEM_BYTES);

    dim3 qkv_grid(128, 3);
    qkv_mma<<<qkv_grid, 256>>>(x, Wk, Wq, Wv);

    attn_mma<<<B_ * (T_ / 64), 256, ATTN_SMEM_BYTES>>>(out);
}